// round 2
// baseline (speedup 1.0000x reference)
#include <cuda_runtime.h>

#define BLK      128
#define NF       32
#define NDOF     29
#define CHUNK    4
#define TS       52     // floats per batch in staging slab: 4 frames * 12 + 4 pad (16B-aligned, bank-safe)

// ---------------------------------------------------------------------------
// Fast sincos: Cody-Waite range reduction + short polys. All FMA-pipe, no MUFU.
// ---------------------------------------------------------------------------
__device__ __forceinline__ void fast_sincos(float a, float &s, float &c) {
    float q  = rintf(a * 0.63661977236758134f);   // a * 2/pi
    int   iq = (int)q;
    float r  = fmaf(q, -1.5707962513e+0f, a);
    r        = fmaf(q, -7.5497894159e-8f, r);
    float r2 = r * r;

    float ps = fmaf(r2, -1.9841270e-4f, 8.3333333e-3f);
    ps       = fmaf(r2, ps, -1.6666667e-1f);
    float sr = fmaf(r * r2, ps, r);

    float pc = fmaf(r2, -1.3888889e-3f, 4.1666668e-2f);
    pc       = fmaf(r2, pc, -5.0e-1f);
    float cr = fmaf(r2, pc, 1.0f);

    bool  sw = (iq & 1);
    float ss = sw ? cr : sr;
    float cc = sw ? sr : cr;
    unsigned sgn_s = ((unsigned)(iq & 2)) << 30;
    unsigned sgn_c = ((unsigned)((iq + 1) & 2)) << 30;
    s = __uint_as_float(__float_as_uint(ss) ^ sgn_s);
    c = __uint_as_float(__float_as_uint(cc) ^ sgn_c);
}

__global__ void __launch_bounds__(BLK, 4)
fk_kernel(const float* __restrict__ ja,        // [B, 29]
          const float* __restrict__ axes,      // [32, 3]
          const float* __restrict__ origins,   // [32, 4, 4]
          const float* __restrict__ mmult,     // [2]
          const float* __restrict__ moff,      // [2]
          const int*   __restrict__ ctrl,      // [29]
          const int*   __restrict__ msrc,      // [2]
          const int*   __restrict__ mdst,      // [2]
          const int*   __restrict__ types,     // [32]
          float*       __restrict__ out,       // [B, 32, 4, 4]
          int Bn)
{
    __shared__ float s_orig[NF][12];
    __shared__ float s_axis[NF][4];
    __shared__ int   s_type[NF];
    __shared__ int   s_slot[NF];
    __shared__ int   s_mslot[NF];
    __shared__ float s_mc[NF][2];
    __shared__ __align__(16) float s_stage[BLK * TS];   // 26.6KB; also temp for raw angles at init
    __shared__ float s_angF[NF * BLK];                  // final angle per (frame, batch)

    const int tid  = threadIdx.x;
    const int lane = tid & 31;
    const int wid  = tid >> 5;
    const int b0   = blockIdx.x * BLK;
    const int gb   = b0 + tid;              // this thread's batch

    // ---- per-frame descriptor setup ----
    if (tid < NF) {
        const int f = tid;
        #pragma unroll
        for (int j = 0; j < 12; ++j) s_orig[f][j] = origins[f * 16 + j];
        s_axis[f][0] = axes[f * 3 + 0];
        s_axis[f][1] = axes[f * 3 + 1];
        s_axis[f][2] = axes[f * 3 + 2];
        s_type[f] = types[f];
        int slot = -1;
        for (int j = 0; j < NDOF; ++j) if (ctrl[j] == f) slot = j;
        s_slot[f] = slot;
        int ms = -1; float mm = 0.f, mo = 0.f;
        for (int m = 0; m < 2; ++m) {
            if (mdst[m] == f) {
                const int sf = msrc[m];
                for (int j = 0; j < NDOF; ++j) if (ctrl[j] == sf) ms = j;
                mm = mmult[m]; mo = moff[m];
            }
        }
        s_mslot[f] = ms; s_mc[f][0] = mm; s_mc[f][1] = mo;
    }

    // ---- stage raw joint angles into s_stage temp (coalesced) ----
    for (int i = tid; i < BLK * NDOF; i += BLK) {
        const int bt = i / NDOF;
        if (b0 + bt < Bn) s_stage[i] = ja[(size_t)b0 * NDOF + i];
    }
    __syncthreads();

    // ---- resolve final per-frame angles for this thread's batch ----
    {
        const float* raw = s_stage + tid * NDOF;
        #pragma unroll
        for (int f = 0; f < NF; ++f) {
            const int slot = s_slot[f];
            float a;
            if (slot >= 0) a = raw[slot];
            else {
                const int ms = s_mslot[f];
                a = (ms >= 0) ? fmaf(raw[ms], s_mc[f][0], s_mc[f][1]) : 0.f;
            }
            s_angF[f * BLK + tid] = a;
        }
    }
    __syncthreads();   // raw temp must be fully consumed before slabs are reused

    // ---- main chain: warp-autonomous from here on ----
    float P[12], S10[12];
    #pragma unroll
    for (int j = 0; j < 12; ++j) P[j] = 0.f;
    P[0] = 1.f; P[5] = 1.f; P[10] = 1.f;    // identity (frame 0 then yields P = L0)
    #pragma unroll
    for (int j = 0; j < 12; ++j) S10[j] = 0.f;

    float* const wslab = s_stage + wid * (32 * TS);
    float4* const out4 = reinterpret_cast<float4*>(out);

    for (int c = 0; c < NF / CHUNK; ++c) {
        // -- phase 1: build all CHUNK local transforms (independent -> big ILP) --
        float L[CHUNK][12];
        #pragma unroll
        for (int ff = 0; ff < CHUNK; ++ff) {
            const int f = c * CHUNK + ff;
            const float a = s_angF[f * BLK + tid];
            const int ty = s_type[f];
            float sn, cs;
            fast_sincos(a, sn, cs);
            if (ty != 1) { sn = 0.f; cs = 1.f; }
            const float kx = s_axis[f][0], ky = s_axis[f][1], kz = s_axis[f][2];
            const float C = 1.0f - cs;
            const float R00 = fmaf(C, kx * kx, cs);
            const float R01 = fmaf(C, kx * ky, -sn * kz);
            const float R02 = fmaf(C, kx * kz,  sn * ky);
            const float R10 = fmaf(C, ky * kx,  sn * kz);
            const float R11 = fmaf(C, ky * ky, cs);
            const float R12 = fmaf(C, ky * kz, -sn * kx);
            const float R20 = fmaf(C, kz * kx, -sn * ky);
            const float R21 = fmaf(C, kz * ky,  sn * kx);
            const float R22 = fmaf(C, kz * kz, cs);
            const float tv = (ty == 2) ? a : 0.f;
            const float t0 = kx * tv, t1 = ky * tv, t2 = kz * tv;
            #pragma unroll
            for (int r = 0; r < 3; ++r) {
                const float O0 = s_orig[f][r * 4 + 0];
                const float O1 = s_orig[f][r * 4 + 1];
                const float O2 = s_orig[f][r * 4 + 2];
                const float O3 = s_orig[f][r * 4 + 3];
                L[ff][r * 4 + 0] = fmaf(O0, R00, fmaf(O1, R10, O2 * R20));
                L[ff][r * 4 + 1] = fmaf(O0, R01, fmaf(O1, R11, O2 * R21));
                L[ff][r * 4 + 2] = fmaf(O0, R02, fmaf(O1, R12, O2 * R22));
                L[ff][r * 4 + 3] = fmaf(O0, t0, fmaf(O1, t1, fmaf(O2, t2, O3)));
            }
        }

        // -- phase 2: serial chain updates + stage into warp-private slab --
        #pragma unroll
        for (int ff = 0; ff < CHUNK; ++ff) {
            const int f = c * CHUNK + ff;
            if (f >= 30) {                    // frames 30,31 both branch off frame 10
                #pragma unroll
                for (int j = 0; j < 12; ++j) P[j] = S10[j];
            }
            #pragma unroll
            for (int r = 0; r < 3; ++r) {
                const float p0 = P[r * 4 + 0], p1 = P[r * 4 + 1];
                const float p2 = P[r * 4 + 2], p3 = P[r * 4 + 3];
                P[r * 4 + 0] = fmaf(p0, L[ff][0], fmaf(p1, L[ff][4], p2 * L[ff][8]));
                P[r * 4 + 1] = fmaf(p0, L[ff][1], fmaf(p1, L[ff][5], p2 * L[ff][9]));
                P[r * 4 + 2] = fmaf(p0, L[ff][2], fmaf(p1, L[ff][6], p2 * L[ff][10]));
                P[r * 4 + 3] = fmaf(p0, L[ff][3], fmaf(p1, L[ff][7], fmaf(p2, L[ff][11], p3)));
            }
            if (f == 10) {
                #pragma unroll
                for (int j = 0; j < 12; ++j) S10[j] = P[j];
            }
            float4* sp = reinterpret_cast<float4*>(wslab + lane * TS + ff * 12);
            sp[0] = make_float4(P[0], P[1], P[2],  P[3]);
            sp[1] = make_float4(P[4], P[5], P[6],  P[7]);
            sp[2] = make_float4(P[8], P[9], P[10], P[11]);
        }

        __syncwarp();

        // -- phase 3: warp-private coalesced flush (2 batches x 256B per iter) --
        #pragma unroll
        for (int it = 0; it < 16; ++it) {
            const int v  = it * 32 + lane;
            const int b  = v >> 4;            // warp-local batch 0..31
            const int fc = (v >> 2) & 3;
            const int r  = v & 3;
            float4 val;
            if (r < 3) val = *reinterpret_cast<const float4*>(wslab + b * TS + fc * 12 + r * 4);
            else       val = make_float4(0.f, 0.f, 0.f, 1.f);
            const int gbat = b0 + (wid << 5) + b;
            if (gbat < Bn)
                out4[((size_t)gbat * NF + (c * CHUNK + fc)) * 4 + r] = val;
        }

        __syncwarp();   // slab may be overwritten by next chunk only after all lanes read it
    }
}

extern "C" void kernel_launch(void* const* d_in, const int* in_sizes, int n_in,
                              void* d_out, int out_size) {
    const float* ja      = (const float*)d_in[0];
    const float* axes    = (const float*)d_in[1];
    const float* origins = (const float*)d_in[2];
    const float* mm      = (const float*)d_in[3];
    const float* mo      = (const float*)d_in[4];
    const int*   ctrl    = (const int*)d_in[5];
    const int*   msrc    = (const int*)d_in[6];
    const int*   mdst    = (const int*)d_in[7];
    const int*   types   = (const int*)d_in[8];
    float*       out     = (float*)d_out;

    const int Bn   = in_sizes[0] / NDOF;
    const int grid = (Bn + BLK - 1) / BLK;
    fk_kernel<<<grid, BLK>>>(ja, axes, origins, mm, mo, ctrl, msrc, mdst, types, out, Bn);
}